// round 10
// baseline (speedup 1.0000x reference)
#include <cuda_runtime.h>
#include <cuda_fp16.h>
#include <cstdint>

#define BATCH 4
#define SEQ   2048
#define DMODEL 1024
#define NHEAD 16
#define DK    64
#define SCALE 0.125f

// ---------------- scratch (device globals; no allocation allowed) ----------------
__device__ __half g_Xh[3][(size_t)BATCH * SEQ * DMODEL];     // fp16 inputs
__device__ __half g_Wh[4][(size_t)DMODEL * DMODEL];          // fp16 weights (q,k,v,o)
__device__ __half g_Qh[(size_t)BATCH * NHEAD * SEQ * DK];    // [b,h,s,dk]
__device__ __half g_Kh[(size_t)BATCH * NHEAD * SEQ * DK];    // [b,h,s,dk]
__device__ __half g_Vt[(size_t)BATCH * NHEAD * DK * SEQ];    // [b,h,dk,s]  (transposed)
__device__ __half g_P [(size_t)BATCH * NHEAD * SEQ * SEQ];   // 512 MB unnormalized probs
__device__ __half g_Ch[(size_t)BATCH * SEQ * DMODEL];        // context fp16 [B,S,D]
__device__ float  g_rowsum[(size_t)BATCH * NHEAD * SEQ];

// =====================================================================
// dst selected inside the kernel: which 0..2 -> g_Xh[which], 3..6 -> g_Wh[which-3]
__global__ __launch_bounds__(256) void cvt_kernel(const float* __restrict__ s,
                                                  int which, int n4) {
    int i = blockIdx.x * 256 + threadIdx.x;
    if (i < n4) {
        __half* d = (which < 3) ? g_Xh[which] : g_Wh[which - 3];
        float4 v = ((const float4*)s)[i];
        __half2* dp = (__half2*)d + i * 2;
        dp[0] = __floats2half2_rn(v.x, v.y);
        dp[1] = __floats2half2_rn(v.z, v.w);
    }
}

// ---------------- mma helpers ----------------
__device__ __forceinline__ uint32_t smaddr(const void* p) {
    return (uint32_t)__cvta_generic_to_shared(p);
}
__device__ __forceinline__ void ldsm4(uint32_t& a0, uint32_t& a1, uint32_t& a2, uint32_t& a3,
                                      uint32_t addr) {
    asm volatile("ldmatrix.sync.aligned.m8n8.x4.shared.b16 {%0,%1,%2,%3}, [%4];\n"
                 : "=r"(a0), "=r"(a1), "=r"(a2), "=r"(a3) : "r"(addr));
}
__device__ __forceinline__ void ldsm2(uint32_t& b0, uint32_t& b1, uint32_t addr) {
    asm volatile("ldmatrix.sync.aligned.m8n8.x2.shared.b16 {%0,%1}, [%2];\n"
                 : "=r"(b0), "=r"(b1) : "r"(addr));
}
__device__ __forceinline__ void mma16816(float* c, uint32_t a0, uint32_t a1, uint32_t a2,
                                         uint32_t a3, uint32_t b0, uint32_t b1) {
    asm volatile("mma.sync.aligned.m16n8k16.row.col.f32.f16.f16.f32 "
                 "{%0,%1,%2,%3}, {%4,%5,%6,%7}, {%8,%9}, {%0,%1,%2,%3};\n"
                 : "+f"(c[0]), "+f"(c[1]), "+f"(c[2]), "+f"(c[3])
                 : "r"(a0), "r"(a1), "r"(a2), "r"(a3), "r"(b0), "r"(b1));
}

#define LDS 40   // padded leading dim (halfs) for 32-wide tiles: conflict-free ldmatrix

// =====================================================================
// 128x128 HMMA GEMM: C = A @ B^T, A [M,kd] row fp16, B [N,kd] row fp16.
// 8 warps: wy=wid>>2 (m 64), wx=wid&3 (n 32). 4x4 mma tiles per warp.
// EPI 0: QKV proj (z=which; V written transposed).  EPI 2: out-proj + bias.
// =====================================================================
template<int EPI>
__global__ __launch_bounds__(256) void mgemm(const float* __restrict__ bias,
                                             float* __restrict__ Cp) {
    __shared__ __align__(16) __half As[2][128 * LDS];
    __shared__ __align__(16) __half Bs[2][128 * LDS];

    const int z = blockIdx.z;
    const __half* A; const __half* B;
    if constexpr (EPI == 0) { A = g_Xh[z]; B = g_Wh[z]; }
    else { A = g_Ch; B = g_Wh[3]; }
    const int lda = DMODEL, ktiles = DMODEL / 32;

    const int tid = threadIdx.x;
    const int m0 = blockIdx.y * 128, n0 = blockIdx.x * 128;
    const int wid = tid >> 5, lane = tid & 31;
    const int wy = wid >> 2, wx = wid & 3;

    const int r0 = tid >> 2, c0 = (tid & 3) * 8;
    const int r1 = (tid + 256) >> 2, c1 = c0;

    const __half* Ag0 = A + (size_t)(m0 + r0) * lda + c0;
    const __half* Ag1 = A + (size_t)(m0 + r1) * lda + c1;
    const __half* Bg0 = B + (size_t)(n0 + r0) * lda + c0;
    const __half* Bg1 = B + (size_t)(n0 + r1) * lda + c1;

    {
        uint4 a0 = *(const uint4*)Ag0, a1 = *(const uint4*)Ag1;
        uint4 b0 = *(const uint4*)Bg0, b1 = *(const uint4*)Bg1;
        *(uint4*)&As[0][r0 * LDS + c0] = a0; *(uint4*)&As[0][r1 * LDS + c1] = a1;
        *(uint4*)&Bs[0][r0 * LDS + c0] = b0; *(uint4*)&Bs[0][r1 * LDS + c1] = b1;
    }
    __syncthreads();

    int aoff[4], boff[4];
#pragma unroll
    for (int mt = 0; mt < 4; mt++)
        aoff[mt] = (wy * 64 + mt * 16 + (lane & 15)) * LDS + (lane >> 4) * 8;
#pragma unroll
    for (int nt = 0; nt < 4; nt++)
        boff[nt] = (wx * 32 + nt * 8 + (lane & 7)) * LDS + ((lane >> 3) & 1) * 8;

    float acc[4][4][4];
#pragma unroll
    for (int i = 0; i < 4; i++)
#pragma unroll
        for (int j = 0; j < 4; j++)
#pragma unroll
            for (int k = 0; k < 4; k++) acc[i][j][k] = 0.f;

    for (int t = 0; t < ktiles; t++) {
        const int cur = t & 1;
        uint4 pa0, pa1, pb0, pb1;
        if (t + 1 < ktiles) {
            int ko = (t + 1) * 32;
            pa0 = *(const uint4*)(Ag0 + ko); pa1 = *(const uint4*)(Ag1 + ko);
            pb0 = *(const uint4*)(Bg0 + ko); pb1 = *(const uint4*)(Bg1 + ko);
        }
#pragma unroll
        for (int ks = 0; ks < 2; ks++) {
            uint32_t af[4][4], bf[4][2];
#pragma unroll
            for (int mt = 0; mt < 4; mt++)
                ldsm4(af[mt][0], af[mt][1], af[mt][2], af[mt][3],
                      smaddr(&As[cur][aoff[mt] + ks * 16]));
#pragma unroll
            for (int nt = 0; nt < 4; nt++)
                ldsm2(bf[nt][0], bf[nt][1], smaddr(&Bs[cur][boff[nt] + ks * 16]));
#pragma unroll
            for (int mt = 0; mt < 4; mt++)
#pragma unroll
                for (int nt = 0; nt < 4; nt++)
                    mma16816(acc[mt][nt], af[mt][0], af[mt][1], af[mt][2], af[mt][3],
                             bf[nt][0], bf[nt][1]);
        }
        if (t + 1 < ktiles) {
            const int nx = cur ^ 1;
            *(uint4*)&As[nx][r0 * LDS + c0] = pa0; *(uint4*)&As[nx][r1 * LDS + c1] = pa1;
            *(uint4*)&Bs[nx][r0 * LDS + c0] = pb0; *(uint4*)&Bs[nx][r1 * LDS + c1] = pb1;
        }
        __syncthreads();
    }

    if constexpr (EPI == 0) {
#pragma unroll
        for (int mt = 0; mt < 4; mt++) {
            int rA = m0 + wy * 64 + mt * 16 + (lane >> 2);
#pragma unroll
            for (int half_ = 0; half_ < 2; half_++) {
                int r = rA + half_ * 8;
                int b = r >> 11, s = r & (SEQ - 1);
#pragma unroll
                for (int nt = 0; nt < 4; nt++) {
                    int c = n0 + wx * 32 + nt * 8 + (lane & 3) * 2;
                    int h = c >> 6, dk = c & 63;
                    float v0 = acc[mt][nt][half_ * 2 + 0];
                    float v1 = acc[mt][nt][half_ * 2 + 1];
                    if (z == 2) {
                        size_t base = ((size_t)(b * NHEAD + h) * DK + dk) * SEQ + s;
                        g_Vt[base] = __float2half_rn(v0);
                        g_Vt[base + SEQ] = __float2half_rn(v1);
                    } else {
                        __half* Out = (z == 0) ? g_Qh : g_Kh;
                        *(__half2*)(Out + ((size_t)(b * NHEAD + h) * SEQ + s) * DK + dk) =
                            __floats2half2_rn(v0, v1);
                    }
                }
            }
        }
    } else {
#pragma unroll
        for (int mt = 0; mt < 4; mt++) {
            int rA = m0 + wy * 64 + mt * 16 + (lane >> 2);
#pragma unroll
            for (int half_ = 0; half_ < 2; half_++) {
                int r = rA + half_ * 8;
#pragma unroll
                for (int nt = 0; nt < 4; nt++) {
                    int c = n0 + wx * 32 + nt * 8 + (lane & 3) * 2;
                    float2 bb = *(const float2*)(bias + c);
                    float2 v = make_float2(acc[mt][nt][half_ * 2 + 0] + bb.x,
                                           acc[mt][nt][half_ * 2 + 1] + bb.y);
                    *(float2*)(Cp + (size_t)r * DMODEL + c) = v;
                }
            }
        }
    }
}

// =====================================================================
// Fused attention: per (q-tile 128, bh). Each warp owns an m16 strip.
// k-loop: S = Q@K^T -> p = exp(S*scale)*mask -> rowsum (regs), store p fp16
// to g_P, reinterpret C-frags as A-frags, ctx_acc += p@V. Epilogue: /rowsum.
// No atomics, no separate ctx pass.
// LDS_K=72 (64-wide K tile), LDS_V=136 (128-wide V tile): conflict-free.
// =====================================================================
#define LDSK 72
#define LDSV 136
__global__ __launch_bounds__(256) void fused_attn(const int* __restrict__ mask) {
    __shared__ __align__(16) __half Ks[128 * LDSK];
    __shared__ __align__(16) __half Vs[64 * LDSV];
    __shared__ float Msf[128];

    const int q0 = blockIdx.x * 128;
    const int bh = blockIdx.y;
    const int b = bh >> 4, h = bh & 15;

    const __half* Qg = g_Qh + (size_t)bh * SEQ * DK;
    const __half* Kg = g_Kh + (size_t)bh * SEQ * DK;
    const __half* Vg = g_Vt + (size_t)bh * DK * SEQ;
    __half* P = g_P + (size_t)bh * SEQ * SEQ;

    const int tid = threadIdx.x;
    const int wid = tid >> 5, lane = tid & 31;
    const int g = lane >> 2;       // row group 0..7
    const int t4 = lane & 3;       // col pair selector

    // ---- stage Q tile (128x64) into Ks, extract per-warp A frags ----
    {
#pragma unroll
        for (int i = 0; i < 4; i++) {
            int idx = tid + i * 256;            // 0..1023
            int row = idx >> 3, c8 = (idx & 7) * 8;
            *(uint4*)&Ks[row * LDSK + c8] = *(const uint4*)(Qg + (size_t)(q0 + row) * DK + c8);
        }
    }
    __syncthreads();
    uint32_t aq[4][4];
    {
        int base = (wid * 16 + (lane & 15)) * LDSK + (lane >> 4) * 8;
#pragma unroll
        for (int kc = 0; kc < 4; kc++)
            ldsm4(aq[kc][0], aq[kc][1], aq[kc][2], aq[kc][3], smaddr(&Ks[base + kc * 16]));
    }
    __syncthreads();   // everyone done reading Q before Ks is reused for K tiles

    float acc_o[8][4];
#pragma unroll
    for (int i = 0; i < 8; i++)
#pragma unroll
        for (int j = 0; j < 4; j++) acc_o[i][j] = 0.f;
    float rs0 = 0.f, rs1 = 0.f;

    // B-frag smem offsets
    int koff[16], voff[8];
#pragma unroll
    for (int nt = 0; nt < 16; nt++)
        koff[nt] = (nt * 8 + (lane & 7)) * LDSK + ((lane >> 3) & 1) * 8;
#pragma unroll
    for (int nt = 0; nt < 8; nt++)
        voff[nt] = (nt * 8 + (lane & 7)) * LDSV + ((lane >> 3) & 1) * 8;

    for (int kt = 0; kt < SEQ / 128; kt++) {
        // ---- stage K (128x64), V (64x128), mask(128) ----
#pragma unroll
        for (int i = 0; i < 4; i++) {
            int idx = tid + i * 256;
            int row = idx >> 3, c8 = (idx & 7) * 8;
            *(uint4*)&Ks[row * LDSK + c8] =
                *(const uint4*)(Kg + (size_t)(kt * 128 + row) * DK + c8);
        }
#pragma unroll
        for (int i = 0; i < 4; i++) {
            int idx = tid + i * 256;
            int row = idx >> 4, c8 = (idx & 15) * 8;
            *(uint4*)&Vs[row * LDSV + c8] =
                *(const uint4*)(Vg + (size_t)row * SEQ + kt * 128 + c8);
        }
        if (tid < 128) Msf[tid] = mask[b * SEQ + kt * 128 + tid] ? 1.f : 0.f;
        __syncthreads();

        // ---- scores: S (m16 x n128), k=64 ----
        float s[16][4];
#pragma unroll
        for (int nt = 0; nt < 16; nt++)
#pragma unroll
            for (int j = 0; j < 4; j++) s[nt][j] = 0.f;
#pragma unroll
        for (int kc = 0; kc < 4; kc++) {
#pragma unroll
            for (int nt = 0; nt < 16; nt++) {
                uint32_t b0, b1;
                ldsm2(b0, b1, smaddr(&Ks[koff[nt] + kc * 16]));
                mma16816(s[nt], aq[kc][0], aq[kc][1], aq[kc][2], aq[kc][3], b0, b1);
            }
        }

        // ---- exp * mask, rowsum, store P, build fp16 A-frags ----
        uint32_t ae[8][4];
        int rgl = q0 + wid * 16 + g;
#pragma unroll
        for (int nt = 0; nt < 16; nt++) {
            int cl = nt * 8 + t4 * 2;
            float m0 = Msf[cl], m1 = Msf[cl + 1];
            float p0 = __expf(s[nt][0] * SCALE) * m0;
            float p1 = __expf(s[nt][1] * SCALE) * m1;
            float p2 = __expf(s[nt][2] * SCALE) * m0;
            float p3 = __expf(s[nt][3] * SCALE) * m1;
            rs0 += p0 + p1;
            rs1 += p2 + p3;
            __half2 h01 = __floats2half2_rn(p0, p1);
            __half2 h23 = __floats2half2_rn(p2, p3);
            *(__half2*)(P + (size_t)rgl * SEQ + kt * 128 + cl) = h01;
            *(__half2*)(P + (size_t)(rgl + 8) * SEQ + kt * 128 + cl) = h23;
            ae[nt >> 1][(nt & 1) * 2 + 0] = *(uint32_t*)&h01;
            ae[nt >> 1][(nt & 1) * 2 + 1] = *(uint32_t*)&h23;
        }

        // ---- ctx: acc_o += p @ V  (m16 x n64, k=128) ----
#pragma unroll
        for (int kc = 0; kc < 8; kc++) {
#pragma unroll
            for (int nt = 0; nt < 8; nt++) {
                uint32_t b0, b1;
                ldsm2(b0, b1, smaddr(&Vs[voff[nt] + kc * 16]));
                mma16816(acc_o[nt], ae[kc][0], ae[kc][1], ae[kc][2], ae[kc][3], b0, b1);
            }
        }
        __syncthreads();
    }

    // ---- reduce rowsum across the quad, write, normalize, store ctx ----
    rs0 += __shfl_xor_sync(0xFFFFFFFFu, rs0, 1);
    rs0 += __shfl_xor_sync(0xFFFFFFFFu, rs0, 2);
    rs1 += __shfl_xor_sync(0xFFFFFFFFu, rs1, 1);
    rs1 += __shfl_xor_sync(0xFFFFFFFFu, rs1, 2);

    int r = q0 + wid * 16 + g;
    if (t4 == 0) {
        g_rowsum[(size_t)bh * SEQ + r] = rs0;
        g_rowsum[(size_t)bh * SEQ + r + 8] = rs1;
    }
    float inv0 = 1.0f / rs0, inv1 = 1.0f / rs1;
#pragma unroll
    for (int nt = 0; nt < 8; nt++) {
        int c = h * DK + nt * 8 + t4 * 2;
        *(__half2*)(g_Ch + ((size_t)(b * SEQ + r)) * DMODEL + c) =
            __floats2half2_rn(acc_o[nt][0] * inv0, acc_o[nt][1] * inv0);
        *(__half2*)(g_Ch + ((size_t)(b * SEQ + r + 8)) * DMODEL + c) =
            __floats2half2_rn(acc_o[nt][2] * inv1, acc_o[nt][3] * inv1);
    }
}

// =====================================================================
// Head-mean of normalized probs (memory-bound).
// =====================================================================
__global__ __launch_bounds__(256) void mean_kernel(float* __restrict__ out_mean) {
    int q = blockIdx.x;
    int b = blockIdx.y;
    int tid = threadIdx.x;

    float2 macc[4];
#pragma unroll
    for (int j = 0; j < 4; j++) macc[j] = make_float2(0.f, 0.f);

#pragma unroll 1
    for (int h = 0; h < NHEAD; h++) {
        const __half2* row = (const __half2*)(g_P + (((size_t)(b * NHEAD + h)) * SEQ + q) * SEQ);
        float inv = 1.0f / g_rowsum[(size_t)(b * NHEAD + h) * SEQ + q];
#pragma unroll
        for (int j = 0; j < 4; j++) {
            float2 f = __half22float2(row[j * 256 + tid]);
            macc[j].x += f.x * inv;
            macc[j].y += f.y * inv;
        }
    }

    float* om = out_mean + ((size_t)(b * SEQ + q)) * SEQ;
    const float invH = 1.0f / NHEAD;
#pragma unroll
    for (int j = 0; j < 4; j++) {
        float2 v = make_float2(macc[j].x * invH, macc[j].y * invH);
        *(float2*)(om + (j * 256 + tid) * 2) = v;
    }
}

// =====================================================================
extern "C" void kernel_launch(void* const* d_in, const int* in_sizes, int n_in,
                              void* d_out, int out_size) {
    const float* query = (const float*)d_in[0];
    const float* key   = (const float*)d_in[1];
    const float* value = (const float*)d_in[2];
    const int*   mask  = (const int*)d_in[3];
    const float* W_q   = (const float*)d_in[4];
    const float* W_k   = (const float*)d_in[5];
    const float* W_v   = (const float*)d_in[6];
    const float* W_o   = (const float*)d_in[7];
    const float* b_o   = (const float*)d_in[8];

    float* out_main = (float*)d_out;                                    // [B,S,D]
    float* out_mean = out_main + (size_t)BATCH * SEQ * DMODEL;          // [B,S,S]

    dim3 blk(256);

    // fp16 conversions
    const int nX4 = BATCH * SEQ * DMODEL / 4;
    const int nW4 = DMODEL * DMODEL / 4;
    cvt_kernel<<<(nX4 + 255) / 256, blk>>>(query, 0, nX4);
    cvt_kernel<<<(nX4 + 255) / 256, blk>>>(key,   1, nX4);
    cvt_kernel<<<(nX4 + 255) / 256, blk>>>(value, 2, nX4);
    cvt_kernel<<<(nW4 + 255) / 256, blk>>>(W_q, 3, nW4);
    cvt_kernel<<<(nW4 + 255) / 256, blk>>>(W_k, 4, nW4);
    cvt_kernel<<<(nW4 + 255) / 256, blk>>>(W_v, 5, nW4);
    cvt_kernel<<<(nW4 + 255) / 256, blk>>>(W_o, 6, nW4);

    // QKV projections (z = which)
    mgemm<0><<<dim3(DMODEL / 128, (BATCH * SEQ) / 128, 3), blk>>>(nullptr, nullptr);

    // fused scores + exp + rowsum + P store + P@V + normalize
    fused_attn<<<dim3(SEQ / 128, BATCH * NHEAD), blk>>>(mask);

    mean_kernel<<<dim3(SEQ, BATCH), blk>>>(out_mean);

    // output projection
    mgemm<2><<<dim3(DMODEL / 128, (BATCH * SEQ) / 128, 1), blk>>>(b_o, out_main);
}

// round 13
// speedup vs baseline: 1.2696x; 1.2696x over previous
#include <cuda_runtime.h>
#include <cuda_fp16.h>
#include <cstdint>

#define BATCH 4
#define SEQ   2048
#define DMODEL 1024
#define NHEAD 16
#define DK    64
#define SCALE 0.125f

// ---------------- scratch (device globals; no allocation allowed) ----------------
__device__ __half g_Xh[3][(size_t)BATCH * SEQ * DMODEL];     // fp16 inputs
__device__ __half g_Wh[4][(size_t)DMODEL * DMODEL];          // fp16 weights (q,k,v,o)
__device__ __half g_Qh[(size_t)BATCH * NHEAD * SEQ * DK];    // [b,h,s,dk]
__device__ __half g_Kh[(size_t)BATCH * NHEAD * SEQ * DK];    // [b,h,s,dk]
__device__ __half g_Vt[(size_t)BATCH * NHEAD * DK * SEQ];    // [b,h,dk,s]  (transposed)
__device__ __half g_P [(size_t)BATCH * NHEAD * SEQ * SEQ];   // 512 MB unnormalized probs
__device__ __half g_Ch[(size_t)BATCH * SEQ * DMODEL];        // context fp16 [B,S,D]
__device__ float  g_rowsum[(size_t)BATCH * NHEAD * SEQ];

// =====================================================================
// single fused fp32->fp16 conversion over all 7 tensors
// =====================================================================
#define NX4 (BATCH * SEQ * DMODEL / 4)     // 2097152
#define NW4 (DMODEL * DMODEL / 4)          // 262144
__global__ __launch_bounds__(256) void cvt_all(
    const float* __restrict__ q, const float* __restrict__ k, const float* __restrict__ v,
    const float* __restrict__ wq, const float* __restrict__ wk,
    const float* __restrict__ wv, const float* __restrict__ wo) {
    int i = blockIdx.x * 256 + threadIdx.x;
    const float* src; __half* dst; int off;
    if (i < 3 * NX4) {
        int w = i / NX4; off = i - w * NX4;
        src = (w == 0) ? q : (w == 1) ? k : v;
        dst = g_Xh[w];
    } else {
        int j = i - 3 * NX4;
        int w = j / NW4; off = j - w * NW4;
        src = (w == 0) ? wq : (w == 1) ? wk : (w == 2) ? wv : wo;
        dst = g_Wh[w];
    }
    float4 val = ((const float4*)src)[off];
    __half2* dp = (__half2*)dst + off * 2;
    dp[0] = __floats2half2_rn(val.x, val.y);
    dp[1] = __floats2half2_rn(val.z, val.w);
}

// ---------------- mma / async helpers ----------------
__device__ __forceinline__ uint32_t smaddr(const void* p) {
    return (uint32_t)__cvta_generic_to_shared(p);
}
__device__ __forceinline__ void ldsm4(uint32_t& a0, uint32_t& a1, uint32_t& a2, uint32_t& a3,
                                      uint32_t addr) {
    asm volatile("ldmatrix.sync.aligned.m8n8.x4.shared.b16 {%0,%1,%2,%3}, [%4];\n"
                 : "=r"(a0), "=r"(a1), "=r"(a2), "=r"(a3) : "r"(addr));
}
__device__ __forceinline__ void ldsm2(uint32_t& b0, uint32_t& b1, uint32_t addr) {
    asm volatile("ldmatrix.sync.aligned.m8n8.x2.shared.b16 {%0,%1}, [%2];\n"
                 : "=r"(b0), "=r"(b1) : "r"(addr));
}
__device__ __forceinline__ void mma16816(float* c, uint32_t a0, uint32_t a1, uint32_t a2,
                                         uint32_t a3, uint32_t b0, uint32_t b1) {
    asm volatile("mma.sync.aligned.m16n8k16.row.col.f32.f16.f16.f32 "
                 "{%0,%1,%2,%3}, {%4,%5,%6,%7}, {%8,%9}, {%0,%1,%2,%3};\n"
                 : "+f"(c[0]), "+f"(c[1]), "+f"(c[2]), "+f"(c[3])
                 : "r"(a0), "r"(a1), "r"(a2), "r"(a3), "r"(b0), "r"(b1));
}
__device__ __forceinline__ void cp_async16(uint32_t s, const void* g) {
    asm volatile("cp.async.cg.shared.global [%0], [%1], 16;\n" :: "r"(s), "l"(g));
}
#define CP_COMMIT() asm volatile("cp.async.commit_group;\n" ::: "memory")
#define CP_WAIT0()  asm volatile("cp.async.wait_group 0;\n" ::: "memory")

#define LDS 40   // padded leading dim (halfs) for 32-wide tiles: conflict-free ldmatrix

// =====================================================================
// 128x128 HMMA GEMM: C = A @ B^T (unchanged from R7 — measured good).
// EPI 0: QKV proj (z=which; V written transposed).  EPI 2: out-proj + bias.
// =====================================================================
template<int EPI>
__global__ __launch_bounds__(256) void mgemm(const float* __restrict__ bias,
                                             float* __restrict__ Cp) {
    __shared__ __align__(16) __half As[2][128 * LDS];
    __shared__ __align__(16) __half Bs[2][128 * LDS];

    const int z = blockIdx.z;
    const __half* A; const __half* B;
    if constexpr (EPI == 0) { A = g_Xh[z]; B = g_Wh[z]; }
    else { A = g_Ch; B = g_Wh[3]; }
    const int lda = DMODEL, ktiles = DMODEL / 32;

    const int tid = threadIdx.x;
    const int m0 = blockIdx.y * 128, n0 = blockIdx.x * 128;
    const int wid = tid >> 5, lane = tid & 31;
    const int wy = wid >> 2, wx = wid & 3;

    const int r0 = tid >> 2, c0 = (tid & 3) * 8;
    const int r1 = (tid + 256) >> 2, c1 = c0;

    const __half* Ag0 = A + (size_t)(m0 + r0) * lda + c0;
    const __half* Ag1 = A + (size_t)(m0 + r1) * lda + c1;
    const __half* Bg0 = B + (size_t)(n0 + r0) * lda + c0;
    const __half* Bg1 = B + (size_t)(n0 + r1) * lda + c1;

    {
        uint4 a0 = *(const uint4*)Ag0, a1 = *(const uint4*)Ag1;
        uint4 b0 = *(const uint4*)Bg0, b1 = *(const uint4*)Bg1;
        *(uint4*)&As[0][r0 * LDS + c0] = a0; *(uint4*)&As[0][r1 * LDS + c1] = a1;
        *(uint4*)&Bs[0][r0 * LDS + c0] = b0; *(uint4*)&Bs[0][r1 * LDS + c1] = b1;
    }
    __syncthreads();

    int aoff[4], boff[4];
#pragma unroll
    for (int mt = 0; mt < 4; mt++)
        aoff[mt] = (wy * 64 + mt * 16 + (lane & 15)) * LDS + (lane >> 4) * 8;
#pragma unroll
    for (int nt = 0; nt < 4; nt++)
        boff[nt] = (wx * 32 + nt * 8 + (lane & 7)) * LDS + ((lane >> 3) & 1) * 8;

    float acc[4][4][4];
#pragma unroll
    for (int i = 0; i < 4; i++)
#pragma unroll
        for (int j = 0; j < 4; j++)
#pragma unroll
            for (int k = 0; k < 4; k++) acc[i][j][k] = 0.f;

    for (int t = 0; t < ktiles; t++) {
        const int cur = t & 1;
        uint4 pa0, pa1, pb0, pb1;
        if (t + 1 < ktiles) {
            int ko = (t + 1) * 32;
            pa0 = *(const uint4*)(Ag0 + ko); pa1 = *(const uint4*)(Ag1 + ko);
            pb0 = *(const uint4*)(Bg0 + ko); pb1 = *(const uint4*)(Bg1 + ko);
        }
#pragma unroll
        for (int ks = 0; ks < 2; ks++) {
            uint32_t af[4][4], bf[4][2];
#pragma unroll
            for (int mt = 0; mt < 4; mt++)
                ldsm4(af[mt][0], af[mt][1], af[mt][2], af[mt][3],
                      smaddr(&As[cur][aoff[mt] + ks * 16]));
#pragma unroll
            for (int nt = 0; nt < 4; nt++)
                ldsm2(bf[nt][0], bf[nt][1], smaddr(&Bs[cur][boff[nt] + ks * 16]));
#pragma unroll
            for (int mt = 0; mt < 4; mt++)
#pragma unroll
                for (int nt = 0; nt < 4; nt++)
                    mma16816(acc[mt][nt], af[mt][0], af[mt][1], af[mt][2], af[mt][3],
                             bf[nt][0], bf[nt][1]);
        }
        if (t + 1 < ktiles) {
            const int nx = cur ^ 1;
            *(uint4*)&As[nx][r0 * LDS + c0] = pa0; *(uint4*)&As[nx][r1 * LDS + c1] = pa1;
            *(uint4*)&Bs[nx][r0 * LDS + c0] = pb0; *(uint4*)&Bs[nx][r1 * LDS + c1] = pb1;
        }
        __syncthreads();
    }

    if constexpr (EPI == 0) {
#pragma unroll
        for (int mt = 0; mt < 4; mt++) {
            int rA = m0 + wy * 64 + mt * 16 + (lane >> 2);
#pragma unroll
            for (int half_ = 0; half_ < 2; half_++) {
                int r = rA + half_ * 8;
                int b = r >> 11, s = r & (SEQ - 1);
#pragma unroll
                for (int nt = 0; nt < 4; nt++) {
                    int c = n0 + wx * 32 + nt * 8 + (lane & 3) * 2;
                    int h = c >> 6, dk = c & 63;
                    float v0 = acc[mt][nt][half_ * 2 + 0];
                    float v1 = acc[mt][nt][half_ * 2 + 1];
                    if (z == 2) {
                        size_t base = ((size_t)(b * NHEAD + h) * DK + dk) * SEQ + s;
                        g_Vt[base] = __float2half_rn(v0);
                        g_Vt[base + SEQ] = __float2half_rn(v1);
                    } else {
                        __half* Out = (z == 0) ? g_Qh : g_Kh;
                        *(__half2*)(Out + ((size_t)(b * NHEAD + h) * SEQ + s) * DK + dk) =
                            __floats2half2_rn(v0, v1);
                    }
                }
            }
        }
    } else {
#pragma unroll
        for (int mt = 0; mt < 4; mt++) {
            int rA = m0 + wy * 64 + mt * 16 + (lane >> 2);
#pragma unroll
            for (int half_ = 0; half_ < 2; half_++) {
                int r = rA + half_ * 8;
#pragma unroll
                for (int nt = 0; nt < 4; nt++) {
                    int c = n0 + wx * 32 + nt * 8 + (lane & 3) * 2;
                    float2 bb = *(const float2*)(bias + c);
                    float2 v = make_float2(acc[mt][nt][half_ * 2 + 0] + bb.x,
                                           acc[mt][nt][half_ * 2 + 1] + bb.y);
                    *(float2*)(Cp + (size_t)r * DMODEL + c) = v;
                }
            }
        }
    }
}

// =====================================================================
// Fused attention, cp.async double-buffered 64-key tiles.
// Per (q-tile 128, bh). Each warp owns an m16 strip.
// iter: wait stage kt -> sync -> issue stage kt+1 -> compute (overlapped).
// S=Q@K^T -> p=exp*mask -> rowsum(regs) -> store P fp16 -> p@V -> /rowsum.
// =====================================================================
#define LDSK 72
#define KKT 64                       // keys per tile
#define NKT (SEQ / KKT)              // 32 tiles
__global__ __launch_bounds__(256) void fused_attn(const int* __restrict__ mask) {
    __shared__ __align__(16) __half Ks[2 * 64 * LDSK];   // also stages Q (128 rows)
    __shared__ __align__(16) __half Vs[2 * 64 * LDSK];
    __shared__ float Msf[SEQ];

    const int q0 = blockIdx.x * 128;
    const int bh = blockIdx.y;
    const int b = bh >> 4, h = bh & 15;

    const __half* Qg = g_Qh + (size_t)bh * SEQ * DK;
    const __half* Kg = g_Kh + (size_t)bh * SEQ * DK;
    const __half* Vg = g_Vt + (size_t)bh * DK * SEQ;
    __half* P = g_P + (size_t)bh * SEQ * SEQ;

    const int tid = threadIdx.x;
    const int wid = tid >> 5, lane = tid & 31;
    const int g = lane >> 2;       // row group 0..7
    const int t4 = lane & 3;       // col pair selector

    // ---- stage Q (128x64) across both Ks buffers + full mask row ----
#pragma unroll
    for (int i = 0; i < 4; i++) {
        int idx = tid + i * 256;               // 0..1023
        int row = idx >> 3, c8 = (idx & 7) * 8;
        *(uint4*)&Ks[row * LDSK + c8] = *(const uint4*)(Qg + (size_t)(q0 + row) * DK + c8);
    }
#pragma unroll
    for (int i = 0; i < SEQ / 256; i++)
        Msf[i * 256 + tid] = mask[b * SEQ + i * 256 + tid] ? 1.f : 0.f;
    __syncthreads();

    uint32_t aq[4][4];
    {
        int base = (wid * 16 + (lane & 15)) * LDSK + (lane >> 4) * 8;
#pragma unroll
        for (int kc = 0; kc < 4; kc++)
            ldsm4(aq[kc][0], aq[kc][1], aq[kc][2], aq[kc][3], smaddr(&Ks[base + kc * 16]));
    }
    __syncthreads();   // Q fully consumed before Ks reused for K tiles

    float acc_o[8][4];
#pragma unroll
    for (int i = 0; i < 8; i++)
#pragma unroll
        for (int j = 0; j < 4; j++) acc_o[i][j] = 0.f;
    float rs0 = 0.f, rs1 = 0.f;

    int koff[8];
#pragma unroll
    for (int nt = 0; nt < 8; nt++)
        koff[nt] = (nt * 8 + (lane & 7)) * LDSK + ((lane >> 3) & 1) * 8;

    // loader indices: 2 x 16B chunks each for K and V per stage
    const int lrow0 = tid >> 3, lc8 = (tid & 7) * 8;          // rows 0..31
    const int lrow1 = (tid + 256) >> 3;                        // rows 32..63

    // ---- prologue: stage 0 ----
    {
        int sb = 0;
        cp_async16(smaddr(&Ks[sb + lrow0 * LDSK + lc8]), Kg + (size_t)lrow0 * DK + lc8);
        cp_async16(smaddr(&Ks[sb + lrow1 * LDSK + lc8]), Kg + (size_t)lrow1 * DK + lc8);
        cp_async16(smaddr(&Vs[sb + lrow0 * LDSK + lc8]), Vg + (size_t)lrow0 * SEQ + lc8);
        cp_async16(smaddr(&Vs[sb + lrow1 * LDSK + lc8]), Vg + (size_t)lrow1 * SEQ + lc8);
        CP_COMMIT();
    }

#pragma unroll 1
    for (int kt = 0; kt < NKT; kt++) {
        CP_WAIT0();
        __syncthreads();

        if (kt + 1 < NKT) {
            int sb = ((kt + 1) & 1) * 64 * LDSK;
            int kb = (kt + 1) * KKT;
            cp_async16(smaddr(&Ks[sb + lrow0 * LDSK + lc8]),
                       Kg + (size_t)(kb + lrow0) * DK + lc8);
            cp_async16(smaddr(&Ks[sb + lrow1 * LDSK + lc8]),
                       Kg + (size_t)(kb + lrow1) * DK + lc8);
            cp_async16(smaddr(&Vs[sb + lrow0 * LDSK + lc8]),
                       Vg + (size_t)lrow0 * SEQ + kb + lc8);
            cp_async16(smaddr(&Vs[sb + lrow1 * LDSK + lc8]),
                       Vg + (size_t)lrow1 * SEQ + kb + lc8);
            CP_COMMIT();
        }

        const int cb = (kt & 1) * 64 * LDSK;

        // ---- scores: m16 x n64, k=64 ----
        float sc[8][4];
#pragma unroll
        for (int nt = 0; nt < 8; nt++)
#pragma unroll
            for (int j = 0; j < 4; j++) sc[nt][j] = 0.f;
#pragma unroll
        for (int kc = 0; kc < 4; kc++) {
#pragma unroll
            for (int nt = 0; nt < 8; nt++) {
                uint32_t b0, b1;
                ldsm2(b0, b1, smaddr(&Ks[cb + koff[nt] + kc * 16]));
                mma16816(sc[nt], aq[kc][0], aq[kc][1], aq[kc][2], aq[kc][3], b0, b1);
            }
        }

        // ---- exp*mask, rowsum, store P, build fp16 A-frags ----
        uint32_t ae[4][4];
        int rgl = q0 + wid * 16 + g;
#pragma unroll
        for (int nt = 0; nt < 8; nt++) {
            int cl = nt * 8 + t4 * 2;
            float m0 = Msf[kt * KKT + cl], m1 = Msf[kt * KKT + cl + 1];
            float p0 = __expf(sc[nt][0] * SCALE) * m0;
            float p1 = __expf(sc[nt][1] * SCALE) * m1;
            float p2 = __expf(sc[nt][2] * SCALE) * m0;
            float p3 = __expf(sc[nt][3] * SCALE) * m1;
            rs0 += p0 + p1;
            rs1 += p2 + p3;
            __half2 h01 = __floats2half2_rn(p0, p1);
            __half2 h23 = __floats2half2_rn(p2, p3);
            *(__half2*)(P + (size_t)rgl * SEQ + kt * KKT + cl) = h01;
            *(__half2*)(P + (size_t)(rgl + 8) * SEQ + kt * KKT + cl) = h23;
            ae[nt >> 1][(nt & 1) * 2 + 0] = *(uint32_t*)&h01;
            ae[nt >> 1][(nt & 1) * 2 + 1] = *(uint32_t*)&h23;
        }

        // ---- ctx: acc_o += p @ V  (m16 x n64, k=64) ----
#pragma unroll
        for (int kc = 0; kc < 4; kc++) {
#pragma unroll
            for (int nt = 0; nt < 8; nt++) {
                uint32_t b0, b1;
                ldsm2(b0, b1, smaddr(&Vs[cb + koff[nt] + kc * 16]));
                mma16816(acc_o[nt], ae[kc][0], ae[kc][1], ae[kc][2], ae[kc][3], b0, b1);
            }
        }
    }

    // ---- reduce rowsum across quad, write, normalize, store ctx ----
    rs0 += __shfl_xor_sync(0xFFFFFFFFu, rs0, 1);
    rs0 += __shfl_xor_sync(0xFFFFFFFFu, rs0, 2);
    rs1 += __shfl_xor_sync(0xFFFFFFFFu, rs1, 1);
    rs1 += __shfl_xor_sync(0xFFFFFFFFu, rs1, 2);

    int r = q0 + wid * 16 + g;
    if (t4 == 0) {
        g_rowsum[(size_t)bh * SEQ + r] = rs0;
        g_rowsum[(size_t)bh * SEQ + r + 8] = rs1;
    }
    float inv0 = 1.0f / rs0, inv1 = 1.0f / rs1;
#pragma unroll
    for (int nt = 0; nt < 8; nt++) {
        int c = h * DK + nt * 8 + t4 * 2;
        *(__half2*)(g_Ch + ((size_t)(b * SEQ + r)) * DMODEL + c) =
            __floats2half2_rn(acc_o[nt][0] * inv0, acc_o[nt][1] * inv0);
        *(__half2*)(g_Ch + ((size_t)(b * SEQ + r + 8)) * DMODEL + c) =
            __floats2half2_rn(acc_o[nt][2] * inv1, acc_o[nt][3] * inv1);
    }
}

// =====================================================================
// Head-mean of normalized probs — uint4 loads (one 16B load/thread/head).
// =====================================================================
__global__ __launch_bounds__(256) void mean_kernel(float* __restrict__ out_mean) {
    int q = blockIdx.x;
    int b = blockIdx.y;
    int tid = threadIdx.x;

    float macc[8];
#pragma unroll
    for (int j = 0; j < 8; j++) macc[j] = 0.f;

#pragma unroll 1
    for (int h = 0; h < NHEAD; h++) {
        const uint4* row = (const uint4*)(g_P + (((size_t)(b * NHEAD + h)) * SEQ + q) * SEQ);
        float inv = 1.0f / g_rowsum[(size_t)(b * NHEAD + h) * SEQ + q];
        uint4 raw = row[tid];
        const __half2* hh = (const __half2*)&raw;
#pragma unroll
        for (int j = 0; j < 4; j++) {
            float2 f = __half22float2(hh[j]);
            macc[j * 2 + 0] += f.x * inv;
            macc[j * 2 + 1] += f.y * inv;
        }
    }

    float* om = out_mean + ((size_t)(b * SEQ + q)) * SEQ + tid * 8;
    const float invH = 1.0f / NHEAD;
    float4 o0 = make_float4(macc[0] * invH, macc[1] * invH, macc[2] * invH, macc[3] * invH);
    float4 o1 = make_float4(macc[4] * invH, macc[5] * invH, macc[6] * invH, macc[7] * invH);
    *(float4*)om = o0;
    *(float4*)(om + 4) = o1;
}

// =====================================================================
extern "C" void kernel_launch(void* const* d_in, const int* in_sizes, int n_in,
                              void* d_out, int out_size) {
    const float* query = (const float*)d_in[0];
    const float* key   = (const float*)d_in[1];
    const float* value = (const float*)d_in[2];
    const int*   mask  = (const int*)d_in[3];
    const float* W_q   = (const float*)d_in[4];
    const float* W_k   = (const float*)d_in[5];
    const float* W_v   = (const float*)d_in[6];
    const float* W_o   = (const float*)d_in[7];
    const float* b_o   = (const float*)d_in[8];

    float* out_main = (float*)d_out;                                    // [B,S,D]
    float* out_mean = out_main + (size_t)BATCH * SEQ * DMODEL;          // [B,S,S]

    dim3 blk(256);

    // single fused fp32->fp16 conversion
    const int ntot = 3 * NX4 + 4 * NW4;
    cvt_all<<<ntot / 256, blk>>>(query, key, value, W_q, W_k, W_v, W_o);

    // QKV projections (z = which)
    mgemm<0><<<dim3(DMODEL / 128, (BATCH * SEQ) / 128, 3), blk>>>(nullptr, nullptr);

    // fused scores + exp + rowsum + P store + P@V + normalize (pipelined)
    fused_attn<<<dim3(SEQ / 128, BATCH * NHEAD), blk>>>(mask);

    mean_kernel<<<dim3(SEQ, BATCH), blk>>>(out_mean);

    // output projection
    mgemm<2><<<dim3(DMODEL / 128, (BATCH * SEQ) / 128, 1), blk>>>(b_o, out_main);
}